// round 14
// baseline (speedup 1.0000x reference)
#include <cuda_runtime.h>
#include <cstdint>

// ---------------------------------------------------------------------------
// QuantumDecoder: z -> tanh(z@W_in) -> 4-qubit circuit Z-expectations ->
//                 relu(@W1) -> sigmoid(@W2)
//
// Post-RY circuit is a fixed 16x16 unitary M:
//   z_q = s0^T Re(M^H Z_q M) s0 = sum_{i<=j} S_q[i,j] s_i s_j.
//
// R13 (= R12 with the missing <cstdint>/uint fix):
//  K1 (front): 1 thread/row, fused per-block sim -> S table. z staged via
//     cp.async (LDGSTS, zero register cost) in 8x16-col double-buffered
//     chunks; smem ~27KB, launch_bounds(128,8) -> 32 warps/SM (2x R11).
//  K2 (gemm): R11-proven, untouched: 4 cols/thread, 224 thr, 16 rows/block,
//     W2 in regs, h staged in smem, per-element exp+rcp sigmoid, __stcs.
// ---------------------------------------------------------------------------

__device__ unsigned long long g_h2[65536 * 8];         // h duplicated as f32x2

// ---- packed f32x2 helpers (Blackwell) -------------------------------------
__device__ __forceinline__ unsigned long long pack2(float x, float y) {
    unsigned long long r;
    asm("mov.b64 %0, {%1, %2};" : "=l"(r) : "f"(x), "f"(y));
    return r;
}
__device__ __forceinline__ void unpack2(unsigned long long v, float& x, float& y) {
    asm("mov.b64 {%0, %1}, %2;" : "=f"(x), "=f"(y) : "l"(v));
}
__device__ __forceinline__ unsigned long long ffma2(unsigned long long a,
                                                    unsigned long long b,
                                                    unsigned long long c) {
    unsigned long long d;
    asm("fma.rn.f32x2 %0, %1, %2, %3;" : "=l"(d) : "l"(a), "l"(b), "l"(c));
    return d;
}
__device__ __forceinline__ float sigmoidf_fast(float x) {
    float e = __expf(-x);                 // MUFU.EX2
    return __fdividef(1.0f, 1.0f + e);    // MUFU.RCP
}
__device__ __forceinline__ float tanhf_fast(float x) {
    x = fminf(fmaxf(x, -15.f), 15.f);     // guard exp overflow
    float e = __expf(-2.f * x);
    return __fdividef(1.f - e, 1.f + e);
}
__device__ __forceinline__ void cp_async16(unsigned int smem_dst, const void* gptr) {
    asm volatile("cp.async.cg.shared.global [%0], [%1], 16;"
                 :: "r"(smem_dst), "l"(gptr) : "memory");
}
__device__ __forceinline__ void cp_async_commit() {
    asm volatile("cp.async.commit_group;" ::: "memory");
}
template <int N>
__device__ __forceinline__ void cp_async_wait() {
    asm volatile("cp.async.wait_group %0;" :: "n"(N) : "memory");
}

// ---------------------------------------------------------------------------
// K1: front-end. 128 rows/block, 1 thread/row; cp.async 16-col z chunks.
// ---------------------------------------------------------------------------
#define ZS 20   // words/row/chunk: 16 data + 4 pad = 5x16B (odd) -> no conflicts

__global__ void __launch_bounds__(128, 8) qd_front_kernel(
    const float* __restrict__ z,   const float* __restrict__ W_in,
    const float* __restrict__ b_in, const float* __restrict__ theta,
    const float* __restrict__ W1,  const float* __restrict__ b1)
{
    __shared__ float  sZ[2][128 * ZS];    // double-buffered 16-col chunk
    __shared__ float4 sWin[128];          // W_in [128][4]
    __shared__ float2 sM[16][16];         // sM[x][j] = <x| fixed-circuit |j>
    __shared__ float4 sS4[136];           // symmetric pair coeffs (4 q's)
    __shared__ float  sW1[32];            // W1 [4][8]
    __shared__ float  sb1[8];
    __shared__ float  sbin[4];

    const int tid = threadIdx.x;
    const int r0  = blockIdx.x * 128;
    const int r   = r0 + tid;
    const float4* zg = (const float4*)z;  // [B][32] float4 view

    const int prow = tid >> 2;            // 0..31 staging row base
    const int pc4  = tid & 3;             // float4 index within 16-col chunk

    unsigned int sz_base[2];
    sz_base[0] = (unsigned int)__cvta_generic_to_shared(&sZ[0][0]);
    sz_base[1] = (unsigned int)__cvta_generic_to_shared(&sZ[1][0]);

    // issue one 16-col chunk: 128 rows x 4 float4, 4 LDGSTS per thread
    auto issue_chunk = [&](int ch) {
        unsigned int base = sz_base[ch & 1];
#pragma unroll
        for (int i = 0; i < 4; i++) {
            int row = i * 32 + prow;
            cp_async16(base + (unsigned int)((row * ZS + pc4 * 4) * 4),
                       zg + (size_t)(r0 + row) * 32 + ch * 4 + pc4);
        }
        cp_async_commit();
    };

    // prologue: chunks 0 and 1 in flight before the sim
    issue_chunk(0);
    issue_chunk(1);

    sWin[tid] = ((const float4*)W_in)[tid];
    if (tid < 32) sW1[tid] = W1[tid];
    if (tid < 8)  sb1[tid] = b1[tid];
    if (tid < 4)  sbin[tid] = b_in[tid];

    // ---- per-block sim of the fixed circuit on basis state |tid> ----------
    if (tid < 16) {
        float2 st[16];
#pragma unroll
        for (int x = 0; x < 16; x++) st[x] = make_float2(0.f, 0.f);
        st[tid] = make_float2(1.f, 0.f);

#pragma unroll
        for (int layer = 0; layer < 2; layer++) {
#pragma unroll
            for (int q = 0; q < 4; q++) {
                float th = theta[layer * 4 + q];
                float ch, sh;
                __sincosf(0.5f * th, &sh, &ch);
                int bit = 1 << q;
#pragma unroll
                for (int a = 0; a < 8; a++) {
                    int i0 = ((a >> q) << (q + 1)) | (a & (bit - 1));
                    int i1 = i0 | bit;
                    float2 x0 = st[i0], x1 = st[i1];
                    // Rx
                    float2 y0 = make_float2(ch * x0.x + sh * x1.y, ch * x0.y - sh * x1.x);
                    float2 y1 = make_float2(ch * x1.x + sh * x0.y, ch * x1.y - sh * x0.x);
                    // Ry
                    float2 z0 = make_float2(ch * y0.x - sh * y1.x, ch * y0.y - sh * y1.y);
                    float2 z1 = make_float2(sh * y0.x + ch * y1.x, sh * y0.y + ch * y1.y);
                    // Rz
                    st[i0] = make_float2(ch * z0.x + sh * z0.y, ch * z0.y - sh * z0.x);
                    st[i1] = make_float2(ch * z1.x - sh * z1.y, ch * z1.y + sh * z1.x);
                }
            }
            const int cs[4] = {0, 1, 2, 3};
            const int ts[4] = {1, 2, 3, 0};
#pragma unroll
            for (int g = 0; g < 4; g++) {
                float2 tmp[16];
                int c = cs[g], t = ts[g];
#pragma unroll
                for (int m = 0; m < 16; m++) tmp[m] = st[m ^ (((m >> c) & 1) << t)];
#pragma unroll
                for (int m = 0; m < 16; m++) st[m] = tmp[m];
            }
        }
#pragma unroll
        for (int x = 0; x < 16; x++) sM[x][tid] = st[x];
    }
    __syncthreads();                      // sM ready

    // ---- S table: 544 entries ---------------------------------------------
    for (int e = tid; e < 544; e += 128) {
        int pair = e >> 2, q = e & 3;
        int i = 0, rem = pair;
        while (rem >= 16 - i) { rem -= 16 - i; i++; }
        int j = i + rem;
        float s = 0.f;
#pragma unroll
        for (int x = 0; x < 16; x++) {
            float2 mi = sM[x][i], mj = sM[x][j];
            float d = mi.x * mj.x + mi.y * mj.y;
            s += ((x >> q) & 1) ? -d : d;
        }
        ((float*)sS4)[pair * 4 + q] = (i == j ? 1.f : 2.f) * s;
    }

    // ---- 1) lat = tanh(z_row @ W_in + b_in), cp.async-pipelined chunks ----
    float ax = sbin[0], ay = sbin[1], az = sbin[2], aw = sbin[3];

#pragma unroll
    for (int ch = 0; ch < 8; ch++) {
        // wait for chunk ch (allow the newer in-flight group to remain)
        if (ch < 7) cp_async_wait<1>();
        else        cp_async_wait<0>();
        __syncthreads();                  // all threads see buf ch&1

        const float4* zr = (const float4*)&sZ[ch & 1][tid * ZS];
#pragma unroll
        for (int k4 = 0; k4 < 4; k4++) {
            float4 zv = zr[k4];
            int k0 = ch * 16 + k4 * 4;
            float4 wa = sWin[k0], wb = sWin[k0 + 1];
            float4 wc = sWin[k0 + 2], wd = sWin[k0 + 3];
            ax = fmaf(zv.x, wa.x, ax); ay = fmaf(zv.x, wa.y, ay);
            az = fmaf(zv.x, wa.z, az); aw = fmaf(zv.x, wa.w, aw);
            ax = fmaf(zv.y, wb.x, ax); ay = fmaf(zv.y, wb.y, ay);
            az = fmaf(zv.y, wb.z, az); aw = fmaf(zv.y, wb.w, aw);
            ax = fmaf(zv.z, wc.x, ax); ay = fmaf(zv.z, wc.y, ay);
            az = fmaf(zv.z, wc.z, az); aw = fmaf(zv.z, wc.w, aw);
            ax = fmaf(zv.w, wd.x, ax); ay = fmaf(zv.w, wd.y, ay);
            az = fmaf(zv.w, wd.z, az); aw = fmaf(zv.w, wd.w, aw);
        }
        if (ch < 6) {
            __syncthreads();              // everyone done reading buf ch&1
            issue_chunk(ch + 2);          // refill it
        }
    }
    float a0 = tanhf_fast(ax), a1 = tanhf_fast(ay);
    float a2 = tanhf_fast(az), a3 = tanhf_fast(aw);

    // ---- 2) s0: real RY product state -------------------------------------
    float c0, s0s, c1, s1s, c2, s2s, c3, s3s;
    __sincosf(0.5f * a0, &s0s, &c0);
    __sincosf(0.5f * a1, &s1s, &c1);
    __sincosf(0.5f * a2, &s2s, &c2);
    __sincosf(0.5f * a3, &s3s, &c3);
    float u0 = c0 * c1, u1 = s0s * c1, u2 = c0 * s1s, u3 = s0s * s1s;
    float v0 = c2 * c3, v1 = s2s * c3, v2 = c2 * s3s, v3 = s2s * s3s;
    float st[16];
    st[0]  = u0 * v0; st[1]  = u1 * v0; st[2]  = u2 * v0; st[3]  = u3 * v0;
    st[4]  = u0 * v1; st[5]  = u1 * v1; st[6]  = u2 * v1; st[7]  = u3 * v1;
    st[8]  = u0 * v2; st[9]  = u1 * v2; st[10] = u2 * v2; st[11] = u3 * v2;
    st[12] = u0 * v3; st[13] = u1 * v3; st[14] = u2 * v3; st[15] = u3 * v3;

    // ---- 3) all 4 quadratic forms via symmetric pair table ----------------
    float zq0 = 0.f, zq1 = 0.f, zq2 = 0.f, zq3 = 0.f;
    {
        int pidx = 0;
#pragma unroll
        for (int i = 0; i < 16; i++) {
            float si = st[i];
#pragma unroll
            for (int j = i; j < 16; j++) {
                float p = si * st[j];
                float4 cv = sS4[pidx++];
                zq0 = fmaf(p, cv.x, zq0);
                zq1 = fmaf(p, cv.y, zq1);
                zq2 = fmaf(p, cv.z, zq2);
                zq3 = fmaf(p, cv.w, zq3);
            }
        }
    }

    // ---- 4) h = relu(qexp @ W1 + b1);  qexp[k] = zq[3-k]; store dup'd -----
    unsigned long long hh[8];
#pragma unroll
    for (int m = 0; m < 8; m++) {
        float t = sb1[m];
        t = fmaf(zq3, sW1[0 * 8 + m], t);
        t = fmaf(zq2, sW1[1 * 8 + m], t);
        t = fmaf(zq1, sW1[2 * 8 + m], t);
        t = fmaf(zq0, sW1[3 * 8 + m], t);
        t = fmaxf(t, 0.f);
        hh[m] = pack2(t, t);
    }
    ulonglong2* hp = (ulonglong2*)(g_h2 + (size_t)r * 8);
    hp[0] = make_ulonglong2(hh[0], hh[1]);
    hp[1] = make_ulonglong2(hh[2], hh[3]);
    hp[2] = make_ulonglong2(hh[4], hh[5]);
    hp[3] = make_ulonglong2(hh[6], hh[7]);
}

// ---------------------------------------------------------------------------
// K2: out = sigmoid(h @ W2 + b2). 4 cols/thread, W2 in regs, h staged in
// smem, per-element exp+rcp sigmoid, evict-first stores. (R11-proven.)
// ---------------------------------------------------------------------------
#define ROWS_PER_BLOCK 16

__global__ void __launch_bounds__(224, 4) qd_gemm_kernel(
    const float* __restrict__ W2, const float* __restrict__ b2,
    float* __restrict__ out)
{
    __shared__ ulonglong2 sh[ROWS_PER_BLOCK * 4];    // 16 rows x 64B

    int t = threadIdx.x;
    int r0 = blockIdx.x * ROWS_PER_BLOCK;

    if (t < ROWS_PER_BLOCK * 4)
        sh[t] = ((const ulonglong2*)g_h2)[(size_t)r0 * 4 + t];

    unsigned long long w[8][2];
    unsigned long long bb0 = 0, bb1 = 0;
    if (t < 196) {
        const float4* W2v = (const float4*)W2;   // [8][196] float4 view
#pragma unroll
        for (int k = 0; k < 8; k++) {
            float4 wv = W2v[k * 196 + t];
            w[k][0] = pack2(wv.x, wv.y);
            w[k][1] = pack2(wv.z, wv.w);
        }
        float4 bv = ((const float4*)b2)[t];
        bb0 = pack2(bv.x, bv.y);
        bb1 = pack2(bv.z, bv.w);
    }
    __syncthreads();
    if (t >= 196) return;

    float* outp = out + (size_t)r0 * 784 + 4 * t;

#pragma unroll 4
    for (int rr = 0; rr < ROWS_PER_BLOCK; rr++) {
        ulonglong2 h01 = sh[rr * 4 + 0];
        ulonglong2 h23 = sh[rr * 4 + 1];
        ulonglong2 h45 = sh[rr * 4 + 2];
        ulonglong2 h67 = sh[rr * 4 + 3];

        unsigned long long a0 = bb0, a1 = bb1;
        a0 = ffma2(h01.x, w[0][0], a0);  a1 = ffma2(h01.x, w[0][1], a1);
        a0 = ffma2(h01.y, w[1][0], a0);  a1 = ffma2(h01.y, w[1][1], a1);
        a0 = ffma2(h23.x, w[2][0], a0);  a1 = ffma2(h23.x, w[2][1], a1);
        a0 = ffma2(h23.y, w[3][0], a0);  a1 = ffma2(h23.y, w[3][1], a1);
        a0 = ffma2(h45.x, w[4][0], a0);  a1 = ffma2(h45.x, w[4][1], a1);
        a0 = ffma2(h45.y, w[5][0], a0);  a1 = ffma2(h45.y, w[5][1], a1);
        a0 = ffma2(h67.x, w[6][0], a0);  a1 = ffma2(h67.x, w[6][1], a1);
        a0 = ffma2(h67.y, w[7][0], a0);  a1 = ffma2(h67.y, w[7][1], a1);

        float f0, f1, f2, f3;
        unpack2(a0, f0, f1);
        unpack2(a1, f2, f3);
        __stcs((float4*)(outp + (size_t)rr * 784),
               make_float4(sigmoidf_fast(f0), sigmoidf_fast(f1),
                           sigmoidf_fast(f2), sigmoidf_fast(f3)));
    }
}

// ---------------------------------------------------------------------------
extern "C" void kernel_launch(void* const* d_in, const int* in_sizes, int n_in,
                              void* d_out, int out_size) {
    const float* z     = (const float*)d_in[0];
    const float* W_in  = (const float*)d_in[1];
    const float* b_in  = (const float*)d_in[2];
    const float* theta = (const float*)d_in[3];
    const float* W1    = (const float*)d_in[4];
    const float* b1    = (const float*)d_in[5];
    const float* W2    = (const float*)d_in[6];
    const float* b2    = (const float*)d_in[7];

    int B = in_sizes[0] / 128;          // 65536
    qd_front_kernel<<<B / 128, 128>>>(z, W_in, b_in, theta, W1, b1);
    qd_gemm_kernel<<<B / ROWS_PER_BLOCK, 224>>>(W2, b2, (float*)d_out);
}

// round 15
// speedup vs baseline: 1.0006x; 1.0006x over previous
#include <cuda_runtime.h>
#include <cstdint>

// ---------------------------------------------------------------------------
// QuantumDecoder: z -> tanh(z@W_in) -> 4-qubit circuit Z-expectations ->
//                 relu(@W1) -> sigmoid(@W2)
//
// Post-RY circuit is a fixed 16x16 unitary M:
//   z_q = s0^T Re(M^H Z_q M) s0 = sum_{i<=j} S_q[i,j] s_i s_j.
//
// R15:
//  K1 (front): R11-proven exactly: 1 thread/row, fused per-block sim ->
//     S table; z register-prefetched + double-buffered smem chunks (6
//     barriers total; chunk0 latency hides under the sim).
//  K2 (gemm): R11 form, ROWS_PER_BLOCK 16 -> 32: halves per-block W2
//     prologue count and W2 L2 re-read traffic (100MB -> 50MB), tail loss
//     ~4% at 3.46 waves.
// ---------------------------------------------------------------------------

__device__ unsigned long long g_h2[65536 * 8];         // h duplicated as f32x2

// ---- packed f32x2 helpers (Blackwell) -------------------------------------
__device__ __forceinline__ unsigned long long pack2(float x, float y) {
    unsigned long long r;
    asm("mov.b64 %0, {%1, %2};" : "=l"(r) : "f"(x), "f"(y));
    return r;
}
__device__ __forceinline__ void unpack2(unsigned long long v, float& x, float& y) {
    asm("mov.b64 {%0, %1}, %2;" : "=f"(x), "=f"(y) : "l"(v));
}
__device__ __forceinline__ unsigned long long ffma2(unsigned long long a,
                                                    unsigned long long b,
                                                    unsigned long long c) {
    unsigned long long d;
    asm("fma.rn.f32x2 %0, %1, %2, %3;" : "=l"(d) : "l"(a), "l"(b), "l"(c));
    return d;
}
__device__ __forceinline__ float sigmoidf_fast(float x) {
    float e = __expf(-x);                 // MUFU.EX2
    return __fdividef(1.0f, 1.0f + e);    // MUFU.RCP
}
__device__ __forceinline__ float tanhf_fast(float x) {
    x = fminf(fmaxf(x, -15.f), 15.f);     // guard exp overflow
    float e = __expf(-2.f * x);
    return __fdividef(1.f - e, 1.f + e);
}

// ---------------------------------------------------------------------------
// K1: front-end. 128 rows/block, 1 thread/row; pipelined 32-col z chunks.
// ---------------------------------------------------------------------------
#define ZS 36   // words per row per chunk buffer (9x16B, odd -> conflict-free LDS.128)

__global__ void __launch_bounds__(128, 4) qd_front_kernel(
    const float* __restrict__ z,   const float* __restrict__ W_in,
    const float* __restrict__ b_in, const float* __restrict__ theta,
    const float* __restrict__ W1,  const float* __restrict__ b1)
{
    __shared__ float  sZ[2][128 * ZS];    // double-buffered 32-col chunk
    __shared__ float4 sWin[128];          // W_in [128][4]
    __shared__ float2 sM[16][16];         // sM[x][j] = <x| fixed-circuit |j>
    __shared__ float4 sS4[136];           // symmetric pair coeffs (4 q's)
    __shared__ float  sW1[32];            // W1 [4][8]
    __shared__ float  sb1[8];
    __shared__ float  sbin[4];

    const int tid = threadIdx.x;
    const int r0  = blockIdx.x * 128;
    const int r   = r0 + tid;
    const float4* zg = (const float4*)z;  // [B][32] float4 view

    sWin[tid] = ((const float4*)W_in)[tid];
    if (tid < 32) sW1[tid] = W1[tid];
    if (tid < 8)  sb1[tid] = b1[tid];
    if (tid < 4)  sbin[tid] = b_in[tid];

    const int prow = tid >> 3;            // cooperative-load row step base
    const int pc4  = tid & 7;             // float4 index within 32-col chunk

    // ---- prefetch chunk 0 into registers (hides under the sim) ------------
    float4 pf[8];
#pragma unroll
    for (int i = 0; i < 8; i++)
        pf[i] = zg[(size_t)(r0 + i * 16 + prow) * 32 + 0 * 8 + pc4];

    // ---- per-block sim of the fixed circuit on basis state |tid> ----------
    if (tid < 16) {
        float2 st[16];
#pragma unroll
        for (int x = 0; x < 16; x++) st[x] = make_float2(0.f, 0.f);
        st[tid] = make_float2(1.f, 0.f);

#pragma unroll
        for (int layer = 0; layer < 2; layer++) {
#pragma unroll
            for (int q = 0; q < 4; q++) {
                float th = theta[layer * 4 + q];
                float ch, sh;
                __sincosf(0.5f * th, &sh, &ch);
                int bit = 1 << q;
#pragma unroll
                for (int a = 0; a < 8; a++) {
                    int i0 = ((a >> q) << (q + 1)) | (a & (bit - 1));
                    int i1 = i0 | bit;
                    float2 x0 = st[i0], x1 = st[i1];
                    // Rx
                    float2 y0 = make_float2(ch * x0.x + sh * x1.y, ch * x0.y - sh * x1.x);
                    float2 y1 = make_float2(ch * x1.x + sh * x0.y, ch * x1.y - sh * x0.x);
                    // Ry
                    float2 z0 = make_float2(ch * y0.x - sh * y1.x, ch * y0.y - sh * y1.y);
                    float2 z1 = make_float2(sh * y0.x + ch * y1.x, sh * y0.y + ch * y1.y);
                    // Rz
                    st[i0] = make_float2(ch * z0.x + sh * z0.y, ch * z0.y - sh * z0.x);
                    st[i1] = make_float2(ch * z1.x - sh * z1.y, ch * z1.y + sh * z1.x);
                }
            }
            const int cs[4] = {0, 1, 2, 3};
            const int ts[4] = {1, 2, 3, 0};
#pragma unroll
            for (int g = 0; g < 4; g++) {
                float2 tmp[16];
                int c = cs[g], t = ts[g];
#pragma unroll
                for (int m = 0; m < 16; m++) tmp[m] = st[m ^ (((m >> c) & 1) << t)];
#pragma unroll
                for (int m = 0; m < 16; m++) st[m] = tmp[m];
            }
        }
#pragma unroll
        for (int x = 0; x < 16; x++) sM[x][tid] = st[x];
    }
    __syncthreads();                      // sM ready

    // ---- S table: 544 entries ---------------------------------------------
    for (int e = tid; e < 544; e += 128) {
        int pair = e >> 2, q = e & 3;
        int i = 0, rem = pair;
        while (rem >= 16 - i) { rem -= 16 - i; i++; }
        int j = i + rem;
        float s = 0.f;
#pragma unroll
        for (int x = 0; x < 16; x++) {
            float2 mi = sM[x][i], mj = sM[x][j];
            float d = mi.x * mj.x + mi.y * mj.y;
            s += ((x >> q) & 1) ? -d : d;
        }
        ((float*)sS4)[pair * 4 + q] = (i == j ? 1.f : 2.f) * s;
    }

    // ---- commit chunk 0, prefetch chunk 1 ---------------------------------
#pragma unroll
    for (int i = 0; i < 8; i++)
        *(float4*)&sZ[0][(i * 16 + prow) * ZS + pc4 * 4] = pf[i];
#pragma unroll
    for (int i = 0; i < 8; i++)
        pf[i] = zg[(size_t)(r0 + i * 16 + prow) * 32 + 1 * 8 + pc4];
    __syncthreads();                      // sZ[0] + sS4 ready

    // ---- 1) lat = tanh(z_row @ W_in + b_in), pipelined chunks -------------
    float ax = sbin[0], ay = sbin[1], az = sbin[2], aw = sbin[3];

#pragma unroll
    for (int ch = 0; ch < 4; ch++) {
        if (ch < 3) {
            // commit prefetched chunk ch+1 into the other buffer
#pragma unroll
            for (int i = 0; i < 8; i++)
                *(float4*)&sZ[(ch + 1) & 1][(i * 16 + prow) * ZS + pc4 * 4] = pf[i];
            if (ch < 2) {
                // issue LDG for chunk ch+2 (consumed after next barrier)
#pragma unroll
                for (int i = 0; i < 8; i++)
                    pf[i] = zg[(size_t)(r0 + i * 16 + prow) * 32 + (ch + 2) * 8 + pc4];
            }
        }
        const float4* zr = (const float4*)&sZ[ch & 1][tid * ZS];
#pragma unroll
        for (int k4 = 0; k4 < 8; k4++) {
            float4 zv = zr[k4];
            int k0 = ch * 32 + k4 * 4;
            float4 wa = sWin[k0], wb = sWin[k0 + 1];
            float4 wc = sWin[k0 + 2], wd = sWin[k0 + 3];
            ax = fmaf(zv.x, wa.x, ax); ay = fmaf(zv.x, wa.y, ay);
            az = fmaf(zv.x, wa.z, az); aw = fmaf(zv.x, wa.w, aw);
            ax = fmaf(zv.y, wb.x, ax); ay = fmaf(zv.y, wb.y, ay);
            az = fmaf(zv.y, wb.z, az); aw = fmaf(zv.y, wb.w, aw);
            ax = fmaf(zv.z, wc.x, ax); ay = fmaf(zv.z, wc.y, ay);
            az = fmaf(zv.z, wc.z, az); aw = fmaf(zv.z, wc.w, aw);
            ax = fmaf(zv.w, wd.x, ax); ay = fmaf(zv.w, wd.y, ay);
            az = fmaf(zv.w, wd.z, az); aw = fmaf(zv.w, wd.w, aw);
        }
        if (ch < 3) __syncthreads();
    }
    float a0 = tanhf_fast(ax), a1 = tanhf_fast(ay);
    float a2 = tanhf_fast(az), a3 = tanhf_fast(aw);

    // ---- 2) s0: real RY product state -------------------------------------
    float c0, s0s, c1, s1s, c2, s2s, c3, s3s;
    __sincosf(0.5f * a0, &s0s, &c0);
    __sincosf(0.5f * a1, &s1s, &c1);
    __sincosf(0.5f * a2, &s2s, &c2);
    __sincosf(0.5f * a3, &s3s, &c3);
    float u0 = c0 * c1, u1 = s0s * c1, u2 = c0 * s1s, u3 = s0s * s1s;
    float v0 = c2 * c3, v1 = s2s * c3, v2 = c2 * s3s, v3 = s2s * s3s;
    float st[16];
    st[0]  = u0 * v0; st[1]  = u1 * v0; st[2]  = u2 * v0; st[3]  = u3 * v0;
    st[4]  = u0 * v1; st[5]  = u1 * v1; st[6]  = u2 * v1; st[7]  = u3 * v1;
    st[8]  = u0 * v2; st[9]  = u1 * v2; st[10] = u2 * v2; st[11] = u3 * v2;
    st[12] = u0 * v3; st[13] = u1 * v3; st[14] = u2 * v3; st[15] = u3 * v3;

    // ---- 3) all 4 quadratic forms via symmetric pair table ----------------
    float zq0 = 0.f, zq1 = 0.f, zq2 = 0.f, zq3 = 0.f;
    {
        int pidx = 0;
#pragma unroll
        for (int i = 0; i < 16; i++) {
            float si = st[i];
#pragma unroll
            for (int j = i; j < 16; j++) {
                float p = si * st[j];
                float4 cv = sS4[pidx++];
                zq0 = fmaf(p, cv.x, zq0);
                zq1 = fmaf(p, cv.y, zq1);
                zq2 = fmaf(p, cv.z, zq2);
                zq3 = fmaf(p, cv.w, zq3);
            }
        }
    }

    // ---- 4) h = relu(qexp @ W1 + b1);  qexp[k] = zq[3-k]; store dup'd -----
    unsigned long long hh[8];
#pragma unroll
    for (int m = 0; m < 8; m++) {
        float t = sb1[m];
        t = fmaf(zq3, sW1[0 * 8 + m], t);
        t = fmaf(zq2, sW1[1 * 8 + m], t);
        t = fmaf(zq1, sW1[2 * 8 + m], t);
        t = fmaf(zq0, sW1[3 * 8 + m], t);
        t = fmaxf(t, 0.f);
        hh[m] = pack2(t, t);
    }
    ulonglong2* hp = (ulonglong2*)(g_h2 + (size_t)r * 8);
    hp[0] = make_ulonglong2(hh[0], hh[1]);
    hp[1] = make_ulonglong2(hh[2], hh[3]);
    hp[2] = make_ulonglong2(hh[4], hh[5]);
    hp[3] = make_ulonglong2(hh[6], hh[7]);
}

// ---------------------------------------------------------------------------
// K2: out = sigmoid(h @ W2 + b2). 4 cols/thread, W2 in regs, h staged in
// smem, per-element exp+rcp sigmoid, evict-first stores. 32 rows/block.
// ---------------------------------------------------------------------------
#define ROWS_PER_BLOCK 32

__global__ void __launch_bounds__(224, 4) qd_gemm_kernel(
    const float* __restrict__ W2, const float* __restrict__ b2,
    float* __restrict__ out)
{
    __shared__ ulonglong2 sh[ROWS_PER_BLOCK * 4];    // 32 rows x 64B

    int t = threadIdx.x;
    int r0 = blockIdx.x * ROWS_PER_BLOCK;

    if (t < ROWS_PER_BLOCK * 4)
        sh[t] = ((const ulonglong2*)g_h2)[(size_t)r0 * 4 + t];

    unsigned long long w[8][2];
    unsigned long long bb0 = 0, bb1 = 0;
    if (t < 196) {
        const float4* W2v = (const float4*)W2;   // [8][196] float4 view
#pragma unroll
        for (int k = 0; k < 8; k++) {
            float4 wv = W2v[k * 196 + t];
            w[k][0] = pack2(wv.x, wv.y);
            w[k][1] = pack2(wv.z, wv.w);
        }
        float4 bv = ((const float4*)b2)[t];
        bb0 = pack2(bv.x, bv.y);
        bb1 = pack2(bv.z, bv.w);
    }
    __syncthreads();
    if (t >= 196) return;

    float* outp = out + (size_t)r0 * 784 + 4 * t;

#pragma unroll 4
    for (int rr = 0; rr < ROWS_PER_BLOCK; rr++) {
        ulonglong2 h01 = sh[rr * 4 + 0];
        ulonglong2 h23 = sh[rr * 4 + 1];
        ulonglong2 h45 = sh[rr * 4 + 2];
        ulonglong2 h67 = sh[rr * 4 + 3];

        unsigned long long a0 = bb0, a1 = bb1;
        a0 = ffma2(h01.x, w[0][0], a0);  a1 = ffma2(h01.x, w[0][1], a1);
        a0 = ffma2(h01.y, w[1][0], a0);  a1 = ffma2(h01.y, w[1][1], a1);
        a0 = ffma2(h23.x, w[2][0], a0);  a1 = ffma2(h23.x, w[2][1], a1);
        a0 = ffma2(h23.y, w[3][0], a0);  a1 = ffma2(h23.y, w[3][1], a1);
        a0 = ffma2(h45.x, w[4][0], a0);  a1 = ffma2(h45.x, w[4][1], a1);
        a0 = ffma2(h45.y, w[5][0], a0);  a1 = ffma2(h45.y, w[5][1], a1);
        a0 = ffma2(h67.x, w[6][0], a0);  a1 = ffma2(h67.x, w[6][1], a1);
        a0 = ffma2(h67.y, w[7][0], a0);  a1 = ffma2(h67.y, w[7][1], a1);

        float f0, f1, f2, f3;
        unpack2(a0, f0, f1);
        unpack2(a1, f2, f3);
        __stcs((float4*)(outp + (size_t)rr * 784),
               make_float4(sigmoidf_fast(f0), sigmoidf_fast(f1),
                           sigmoidf_fast(f2), sigmoidf_fast(f3)));
    }
}

// ---------------------------------------------------------------------------
extern "C" void kernel_launch(void* const* d_in, const int* in_sizes, int n_in,
                              void* d_out, int out_size) {
    const float* z     = (const float*)d_in[0];
    const float* W_in  = (const float*)d_in[1];
    const float* b_in  = (const float*)d_in[2];
    const float* theta = (const float*)d_in[3];
    const float* W1    = (const float*)d_in[4];
    const float* b1    = (const float*)d_in[5];
    const float* W2    = (const float*)d_in[6];
    const float* b2    = (const float*)d_in[7];

    int B = in_sizes[0] / 128;          // 65536
    qd_front_kernel<<<B / 128, 128>>>(z, W_in, b_in, theta, W1, b1);
    qd_gemm_kernel<<<B / ROWS_PER_BLOCK, 224>>>(W2, b2, (float*)d_out);
}